// round 12
// baseline (speedup 1.0000x reference)
#include <cuda_runtime.h>
#include <cuda_bf16.h>
#include <cstdint>

// ============================================================================
// NegativeContrastiveLoss: x[8192,256] fp32 ->
//   xn = x / max(||x||_2, 1e-12)  (rows)
//   S  = xn @ xn^T / 0.1 ; E = exp(S) with diag zeroed
//   loss = mean_i log( sum_j E_ij / (N-1) + 1e-8 )
//
// R11: software-pipelined fragment loads in the GEMM mainloop (A double-
//      buffered across ks, B rolling 1 group ahead) to hide LDSM latency;
//      k_normalize does 2 rows/warp for 2x MLP.
//      Keeps: symmetry (2080 upper-tri 128x128 tiles, row+col sums),
//      3-stage cp.async pipeline, occupancy-2 mma.sync mainloop.
// ============================================================================

#define NROWS 8192
#define DIM   256
#define TAU_INV_LOG2E 14.4269504088896340736f   // (1/0.1) * log2(e)
#define EPS   1e-8f

__device__ __align__(256) __nv_bfloat16 g_xn[NROWS * DIM];   // 4 MB, L2-resident
__device__ float g_rowsum[NROWS];

static __device__ __forceinline__ unsigned smem_u32(const void* p) {
    unsigned a;
    asm("{ .reg .u64 t; cvta.to.shared.u64 t, %1; cvt.u32.u64 %0, t; }" : "=r"(a) : "l"(p));
    return a;
}
static __device__ __forceinline__ void cp_async16(unsigned saddr, const void* gptr) {
    asm volatile("cp.async.cg.shared.global [%0], [%1], 16;"
                 :: "r"(saddr), "l"(gptr) : "memory");
}
static __device__ __forceinline__ void ldmatrix_x4(unsigned& r0, unsigned& r1,
                                                   unsigned& r2, unsigned& r3,
                                                   unsigned addr) {
    asm volatile("ldmatrix.sync.aligned.m8n8.x4.shared.b16 {%0,%1,%2,%3}, [%4];"
                 : "=r"(r0), "=r"(r1), "=r"(r2), "=r"(r3) : "r"(addr));
}
static __device__ __forceinline__ void mma_16816(float* c, const unsigned* a,
                                                 const unsigned* b) {
    asm volatile(
        "mma.sync.aligned.m16n8k16.row.col.f32.bf16.bf16.f32 "
        "{%0,%1,%2,%3}, {%4,%5,%6,%7}, {%8,%9}, {%0,%1,%2,%3};"
        : "+f"(c[0]), "+f"(c[1]), "+f"(c[2]), "+f"(c[3])
        : "r"(a[0]), "r"(a[1]), "r"(a[2]), "r"(a[3]), "r"(b[0]), "r"(b[1]));
}
static __device__ __forceinline__ float ex2f(float v) {
    float e;
    asm("ex2.approx.f32 %0, %1;" : "=f"(e) : "f"(v));
    return e;
}

// ---------------------------------------------------------------------------
// Kernel 1: row L2-normalize -> bf16; zero rowsum and out[0].
// 2 rows per warp (4 independent 16B loads in flight per thread).
// ---------------------------------------------------------------------------
__global__ __launch_bounds__(256) void k_normalize(const float* __restrict__ x,
                                                   float* __restrict__ out) {
    int tid = threadIdx.x;
    int gt = blockIdx.x * 256 + tid;
    if (gt < NROWS) g_rowsum[gt] = 0.0f;
    if (gt == 0) out[0] = 0.0f;

    int wg   = blockIdx.x * 8 + (tid >> 5);      // 512 blocks * 8 warps = 4096
    int lane = tid & 31;
    int r0 = wg * 2, r1 = r0 + 1;
    const float4* x0 = reinterpret_cast<const float4*>(x) + (size_t)r0 * (DIM / 4);
    const float4* x1 = reinterpret_cast<const float4*>(x) + (size_t)r1 * (DIM / 4);
    float4 a0 = x0[lane * 2 + 0];
    float4 b0 = x0[lane * 2 + 1];
    float4 a1 = x1[lane * 2 + 0];
    float4 b1 = x1[lane * 2 + 1];

    float s0 = a0.x * a0.x + a0.y * a0.y + a0.z * a0.z + a0.w * a0.w +
               b0.x * b0.x + b0.y * b0.y + b0.z * b0.z + b0.w * b0.w;
    float s1 = a1.x * a1.x + a1.y * a1.y + a1.z * a1.z + a1.w * a1.w +
               b1.x * b1.x + b1.y * b1.y + b1.z * b1.z + b1.w * b1.w;
#pragma unroll
    for (int o = 16; o; o >>= 1) {
        s0 += __shfl_xor_sync(0xFFFFFFFFu, s0, o);
        s1 += __shfl_xor_sync(0xFFFFFFFFu, s1, o);
    }
    float sc0 = 1.0f / fmaxf(sqrtf(s0), 1e-12f);
    float sc1 = 1.0f / fmaxf(sqrtf(s1), 1e-12f);

    __nv_bfloat162 q0 = __floats2bfloat162_rn(a0.x * sc0, a0.y * sc0);
    __nv_bfloat162 q1 = __floats2bfloat162_rn(a0.z * sc0, a0.w * sc0);
    __nv_bfloat162 q2 = __floats2bfloat162_rn(b0.x * sc0, b0.y * sc0);
    __nv_bfloat162 q3 = __floats2bfloat162_rn(b0.z * sc0, b0.w * sc0);
    uint4 o0;
    o0.x = *reinterpret_cast<unsigned*>(&q0);
    o0.y = *reinterpret_cast<unsigned*>(&q1);
    o0.z = *reinterpret_cast<unsigned*>(&q2);
    o0.w = *reinterpret_cast<unsigned*>(&q3);
    reinterpret_cast<uint4*>(g_xn)[r0 * (DIM / 8) + lane] = o0;

    __nv_bfloat162 u0 = __floats2bfloat162_rn(a1.x * sc1, a1.y * sc1);
    __nv_bfloat162 u1 = __floats2bfloat162_rn(a1.z * sc1, a1.w * sc1);
    __nv_bfloat162 u2 = __floats2bfloat162_rn(b1.x * sc1, b1.y * sc1);
    __nv_bfloat162 u3 = __floats2bfloat162_rn(b1.z * sc1, b1.w * sc1);
    uint4 o1;
    o1.x = *reinterpret_cast<unsigned*>(&u0);
    o1.y = *reinterpret_cast<unsigned*>(&u1);
    o1.z = *reinterpret_cast<unsigned*>(&u2);
    o1.w = *reinterpret_cast<unsigned*>(&u3);
    reinterpret_cast<uint4*>(g_xn)[r1 * (DIM / 8) + lane] = o1;
}

// ---------------------------------------------------------------------------
// Kernel 2: fused GEMM + exp + row/col sums, upper-triangular tiles only.
//
// CTA tile 128x128, K=256 in 4 chunks of 64, 3-stage cp.async pipeline
// (96 KB smem, one __syncthreads per chunk, issue-before-compute).
// Mainloop software-pipelines fragments: A frags double-buffered across ks;
// B frag groups (ldmatrix.x4 = 2 n8-frags) roll 1 group ahead of their MMAs.
// 8 warps as 4(M) x 2(N), warp tile 32x64.
// ---------------------------------------------------------------------------
#define STAGE_BYTES 32768
#define SMEM_TOT    98304           // 3 stages
#define NB 64
#define NTILES (NB * (NB + 1) / 2)  // 2080
#define NKC 4                        // K chunks of 64

__global__ __launch_bounds__(256, 2) void k_gemm() {
    extern __shared__ char smem[];
    unsigned sb = smem_u32(smem);
    int tid  = threadIdx.x;
    int wid  = tid >> 5, lane = tid & 31;

    // triangular decode: k -> (bi, bj), bi <= bj
    int k = blockIdx.x;
    int bi = (int)floorf((float)NB + 0.5f -
                         sqrtf(((float)NB + 0.5f) * ((float)NB + 0.5f) - 2.0f * (float)k));
    while (NB * (bi + 1) - ((bi + 1) * bi) / 2 <= k) bi++;
    while (NB * bi - (bi * (bi - 1)) / 2 > k) bi--;
    int bj = bi + (k - (NB * bi - (bi * (bi - 1)) / 2));
    bool diag = (bi == bj);

    int warp_m = (wid & 3) * 32;
    int warp_n = (wid >> 2) * 64;

    // per-thread cp.async coords: 4 iters x 256 thr = 1024 x 16B per 128x64 buf
    int lr = tid >> 3;
    int lc = tid & 7;
    unsigned ssw = (unsigned)((lc ^ (lr & 7)) << 4);
    const char* gA = reinterpret_cast<const char*>(g_xn) + (size_t)(bi * 128 + lr) * 512 + lc * 16;
    const char* gB = reinterpret_cast<const char*>(g_xn) + (size_t)(bj * 128 + lr) * 512 + lc * 16;

#define ISSUE_STAGE(kc, buf)                                                     \
    do {                                                                         \
        unsigned ab_ = sb + (buf) * STAGE_BYTES;                                 \
        unsigned bb_ = ab_ + 16384;                                              \
        _Pragma("unroll")                                                        \
        for (int it = 0; it < 4; it++)                                           \
            cp_async16(ab_ + (unsigned)(lr + it * 32) * 128 + ssw,               \
                       gA + (size_t)it * 32 * 512 + (kc) * 128);                 \
        _Pragma("unroll")                                                        \
        for (int it = 0; it < 4; it++)                                           \
            cp_async16(bb_ + (unsigned)(lr + it * 32) * 128 + ssw,               \
                       gB + (size_t)it * 32 * 512 + (kc) * 128);                 \
        asm volatile("cp.async.commit_group;" ::: "memory");                     \
    } while (0)

// A fragments for one ks (both mf): 8 regs
#define LOAD_A(dst, ab_, ks)                                                     \
    do {                                                                         \
        _Pragma("unroll")                                                        \
        for (int mf_ = 0; mf_ < 2; mf_++) {                                      \
            int r_ = warp_m + mf_ * 16 + (lane & 15);                            \
            int ch_ = (ks) * 2 + (lane >> 4);                                    \
            ldmatrix_x4((dst)[mf_][0], (dst)[mf_][1], (dst)[mf_][2], (dst)[mf_][3], \
                        ab_ + r_ * 128 + ((ch_ ^ (r_ & 7)) << 4));               \
        }                                                                        \
    } while (0)

// B fragment group p for one ks (2 n8-frags): 4 regs
#define LOAD_B(dst, bb_, ks, p)                                                  \
    do {                                                                         \
        int g_ = lane >> 3;                                                      \
        int r_ = warp_n + (p) * 16 + (g_ >> 1) * 8 + (lane & 7);                 \
        int ch_ = (ks) * 2 + (g_ & 1);                                           \
        ldmatrix_x4((dst)[0], (dst)[1], (dst)[2], (dst)[3],                      \
                    bb_ + r_ * 128 + ((ch_ ^ (r_ & 7)) << 4));                   \
    } while (0)

    float acc[2][8][4];
#pragma unroll
    for (int mf = 0; mf < 2; mf++)
#pragma unroll
        for (int nf = 0; nf < 8; nf++)
#pragma unroll
            for (int j = 0; j < 4; j++) acc[mf][nf][j] = 0.0f;

    // prologue: chunks 0,1 in flight (buffers 0,1)
    ISSUE_STAGE(0, 0);
    ISSUE_STAGE(1, 1);

#pragma unroll
    for (int kc = 0; kc < NKC; kc++) {
        if (kc < NKC - 1) asm volatile("cp.async.wait_group 1;" ::: "memory");
        else              asm volatile("cp.async.wait_group 0;" ::: "memory");
        __syncthreads();   // chunk kc visible; all warps past iter kc-1

        if (kc + 2 < NKC) ISSUE_STAGE(kc + 2, (kc + 2) % 3);

        unsigned ab = sb + (kc % 3) * STAGE_BYTES;
        unsigned bb = ab + 16384;

        unsigned a_frag[2][2][4];   // [ks parity][mf][frag]
        unsigned b_frag[2][4];      // rolling group buffer

        LOAD_A(a_frag[0], ab, 0);
        LOAD_B(b_frag[0], bb, 0, 0);

#pragma unroll
        for (int ks = 0; ks < 4; ks++) {
            if (ks < 3) LOAD_A(a_frag[(ks & 1) ^ 1], ab, ks + 1);
#pragma unroll
            for (int p = 0; p < 4; p++) {
                if (p < 3)          LOAD_B(b_frag[(p + 1) & 1], bb, ks, p + 1);
                else if (ks < 3)    LOAD_B(b_frag[0],           bb, ks + 1, 0);
                // 4 MMAs for group p: nf = 2p, 2p+1 across both mf
#pragma unroll
                for (int mf = 0; mf < 2; mf++) {
                    mma_16816(acc[mf][p * 2 + 0], a_frag[ks & 1][mf], &b_frag[p & 1][0]);
                    mma_16816(acc[mf][p * 2 + 1], a_frag[ks & 1][mf], &b_frag[p & 1][2]);
                }
            }
        }
    }

    // ---- epilogue: exp, diag zero, row sums + (off-diag) column sums ----
    __syncthreads();
    float* colsum = reinterpret_cast<float*>(smem);
    if (!diag) {
        if (tid < 128) colsum[tid] = 0.0f;
        __syncthreads();
    }

    float rs[4] = {0.0f, 0.0f, 0.0f, 0.0f};
    int lrow = lane >> 2;
#pragma unroll
    for (int nf = 0; nf < 8; nf++) {
        float c0 = 0.0f, c1 = 0.0f;
        int gcol0 = bj * 128 + warp_n + nf * 8 + (lane & 3) * 2;
#pragma unroll
        for (int mf = 0; mf < 2; mf++) {
            int grow0 = bi * 128 + warp_m + mf * 16 + lrow;
            float e0 = ex2f(acc[mf][nf][0] * TAU_INV_LOG2E);
            float e1 = ex2f(acc[mf][nf][1] * TAU_INV_LOG2E);
            float e2 = ex2f(acc[mf][nf][2] * TAU_INV_LOG2E);
            float e3 = ex2f(acc[mf][nf][3] * TAU_INV_LOG2E);
            if (diag) {
                e0 = (gcol0     == grow0    ) ? 0.0f : e0;
                e1 = (gcol0 + 1 == grow0    ) ? 0.0f : e1;
                e2 = (gcol0     == grow0 + 8) ? 0.0f : e2;
                e3 = (gcol0 + 1 == grow0 + 8) ? 0.0f : e3;
            }
            rs[mf * 2 + 0] += e0 + e1;
            rs[mf * 2 + 1] += e2 + e3;
            c0 += e0 + e2;
            c1 += e1 + e3;
        }
        if (!diag) {
#pragma unroll
            for (int o = 4; o <= 16; o <<= 1) {
                c0 += __shfl_xor_sync(0xFFFFFFFFu, c0, o);
                c1 += __shfl_xor_sync(0xFFFFFFFFu, c1, o);
            }
            if (lane < 4) {
                int cc = warp_n + nf * 8 + lane * 2;
                atomicAdd(&colsum[cc],     c0);
                atomicAdd(&colsum[cc + 1], c1);
            }
        }
    }

#pragma unroll
    for (int o = 1; o <= 2; o <<= 1)
#pragma unroll
        for (int j = 0; j < 4; j++)
            rs[j] += __shfl_xor_sync(0xFFFFFFFFu, rs[j], o);
    if ((lane & 3) == 0) {
        int r0 = bi * 128 + warp_m + lrow;
        atomicAdd(&g_rowsum[r0],      rs[0]);
        atomicAdd(&g_rowsum[r0 + 8],  rs[1]);
        atomicAdd(&g_rowsum[r0 + 16], rs[2]);
        atomicAdd(&g_rowsum[r0 + 24], rs[3]);
    }

    if (!diag) {
        __syncthreads();
        if (tid < 128) atomicAdd(&g_rowsum[bj * 128 + tid], colsum[tid]);
    }
#undef ISSUE_STAGE
#undef LOAD_A
#undef LOAD_B
}

// ---------------------------------------------------------------------------
// Kernel 3 (parallel): out[0] += block partial of mean log(rowsum/(N-1)+eps)
// ---------------------------------------------------------------------------
__global__ __launch_bounds__(256) void k_reduce(float* __restrict__ out) {
    __shared__ float sh[8];
    int tid = threadIdx.x;
    int i = blockIdx.x * 256 + tid;
    float s = logf(g_rowsum[i] * (1.0f / (float)(NROWS - 1)) + EPS);
#pragma unroll
    for (int o = 16; o; o >>= 1) s += __shfl_xor_sync(0xFFFFFFFFu, s, o);
    if ((tid & 31) == 0) sh[tid >> 5] = s;
    __syncthreads();
    if (tid == 0) {
        float t = 0.0f;
#pragma unroll
        for (int j = 0; j < 8; j++) t += sh[j];
        atomicAdd(out, t * (1.0f / (float)NROWS));
    }
}

// ---------------------------------------------------------------------------
extern "C" void kernel_launch(void* const* d_in, const int* in_sizes, int n_in,
                              void* d_out, int out_size) {
    (void)in_sizes; (void)n_in; (void)out_size;
    const float* x = (const float*)d_in[0];

    cudaFuncSetAttribute(k_gemm, cudaFuncAttributeMaxDynamicSharedMemorySize, SMEM_TOT);

    k_normalize<<<NROWS / 16, 256>>>(x, (float*)d_out);
    k_gemm<<<NTILES, 256, SMEM_TOT>>>();
    k_reduce<<<NROWS / 256, 256>>>((float*)d_out);
}